// round 6
// baseline (speedup 1.0000x reference)
#include <cuda_runtime.h>

// Problem constants (from reference)
#define SEQ    4096
#define CIN    7
#define NK     586        // 585 regular kernels + 1 "last"
#define GLEN   12288      // SEQ * KW(3)
#define HP     12289      // output positions per channel-kernel row
#define GPITCH 12304      // GLEN + 16 (4 left pad + right slack), keeps 16B alignment
#define CTOT   4096       // 7*585 + 1
#define NQ     1024       // c-quads
#define HTILE  16

typedef unsigned long long u64;

// Scratch (allocation-free rule: __device__ globals)
__device__ u64   g_Gdup[CIN * GPITCH];   // duplicated signal: (g,g) as f32x2, g[i] = g_ch[i-4]
__device__ float g_Wmid[NK * 8];         // middle column of each 8x3 kernel (slow path)
__device__ ulonglong2 g_Wq[NQ * 8];      // per-quad packed weights: {(w_c0,w_c1),(w_c2,w_c3)} per tap

__device__ __forceinline__ u64 pk2(float lo, float hi) {
    u64 r; asm("mov.b64 %0, {%1,%2};" : "=l"(r) : "f"(lo), "f"(hi)); return r;
}
__device__ __forceinline__ u64 fma2(u64 a, u64 b, u64 c) {
    u64 d; asm("fma.rn.f32x2 %0, %1, %2, %3;" : "=l"(d) : "l"(a), "l"(b), "l"(c)); return d;
}

// ---- fused prep: mid-column weights, per-quad packed weights, duplicated gathered signal ----
__global__ void prep(const float* __restrict__ x, const float* __restrict__ kernels) {
    int idx = blockIdx.x * blockDim.x + threadIdx.x;
    if (idx < NK * 8) {
        int k = idx >> 3, a = idx & 7;
        g_Wmid[idx] = kernels[k * 24 + a * 3 + 1];
    }
    if (idx < NQ * 8) {
        int q = idx >> 3, a = idx & 7;
        float w[4];
#pragma unroll
        for (int j = 0; j < 4; j++) {
            int c = 4 * q + j;
            int k = (c == CTOT - 1) ? 585 : (c % 585);
            w[j] = kernels[k * 24 + a * 3 + 1];
        }
        ulonglong2 v; v.x = pk2(w[0], w[1]); v.y = pk2(w[2], w[3]);
        g_Wq[idx] = v;
    }
    if (idx < CIN * GPITCH) {
        int ch = idx / GPITCH;
        int i  = idx - ch * GPITCH;
        int t  = i - 4;
        float v = 0.f;
        if (t >= 0 && t < GLEN) {
            int s = t / 3;
            int j = t - s * 3;
            int src = s + j;
            if (src > SEQ - 1) src = SEQ - 1;
            v = x[src * CIN + ch];
        }
        g_Gdup[idx] = pk2(v, v);
    }
}

// ---- main kernel: one c-quad per thread, HTILE rows, one STG.128 per row,
//      window loaded pre-duplicated (no packing MOVs), 84-reg budget (3 CTAs/SM) ----
__global__ void __launch_bounds__(256, 3) conv_main(float* __restrict__ out) {
    const int tid = threadIdx.x;
    const int q   = blockIdx.x * 256 + tid;     // [0, 1024), grid.x = 4
    const int c0  = q * 4;
    const int h0  = blockIdx.y * HTILE;

    const int ch0 = c0 / 585;
    const int c3  = c0 + 3;
    const int ch3 = (c3 == CTOT - 1) ? 0 : c3 / 585;

    const bool uniform  = (ch0 == ch3);
    const bool fulltile = (h0 + HTILE <= HP);

    if (uniform && fulltile) {
        // 8 taps x 2 packed weight pairs per quad (32 regs)
        u64 W0[8], W1[8];
        {
            const ulonglong2* wq = &g_Wq[q * 8];
#pragma unroll
            for (int a = 0; a < 8; a++) { ulonglong2 t = wq[a]; W0[a] = t.x; W1[a] = t.y; }
        }

        const u64* __restrict__ gp = &g_Gdup[ch0 * GPITCH + h0];   // 16B-aligned (h0 mult of 16)

        // Sliding window of 12 duplicated values (24 regs), loaded as LDG.128 pairs
        u64 P[12];
        {
            ulonglong2 a0 = *(const ulonglong2*)(gp);
            ulonglong2 a1 = *(const ulonglong2*)(gp + 2);
            ulonglong2 a2 = *(const ulonglong2*)(gp + 4);
            ulonglong2 a3 = *(const ulonglong2*)(gp + 6);
            ulonglong2 a4 = *(const ulonglong2*)(gp + 8);
            ulonglong2 a5 = *(const ulonglong2*)(gp + 10);
            P[0] = a0.x; P[1] = a0.y; P[2] = a1.x; P[3] = a1.y;
            P[4] = a2.x; P[5] = a2.y; P[6] = a3.x; P[7] = a3.y;
            P[8] = a4.x; P[9] = a4.y; P[10] = a5.x; P[11] = a5.y;
        }

        char* op = (char*)(out + (size_t)h0 * CTOT + c0);
#pragma unroll
        for (int hb = 0; hb < HTILE; hb += 4) {
            ulonglong2 n0, n1;
            if (hb < HTILE - 4) {
                n0 = *(const ulonglong2*)(gp + hb + 12);
                n1 = *(const ulonglong2*)(gp + hb + 14);
            }
#pragma unroll
            for (int u = 0; u < 4; u++) {
                u64 a0 = 0ull, a1 = 0ull;
#pragma unroll
                for (int a = 0; a < 8; a++) {
                    u64 g2 = P[u + a];
                    a0 = fma2(g2, W0[a], a0);
                    a1 = fma2(g2, W1[a], a1);
                }
                ulonglong2 st; st.x = a0; st.y = a1;
                *(ulonglong2*)op = st;                  // STG.128: out[h][c0..c0+3]
                op += CTOT * sizeof(float);
            }
            if (hb < HTILE - 4) {
#pragma unroll
                for (int i = 0; i < 8; i++) P[i] = P[i + 4];
                P[8] = n0.x; P[9] = n0.y; P[10] = n1.x; P[11] = n1.y;
            }
        }
    } else {
        // Slow path: channel-crossing quads (7 of 1024) and the 1-row tail tile.
        int hEnd = min(h0 + HTILE, HP);
        int chv[4], kkv[4];
#pragma unroll
        for (int j = 0; j < 4; j++) {
            int c = c0 + j;
            if (c == CTOT - 1) { chv[j] = 0; kkv[j] = 585; }
            else               { chv[j] = c / 585; kkv[j] = c % 585; }
        }
        for (int h = h0; h < hEnd; h++) {
            float acc[4];
#pragma unroll
            for (int j = 0; j < 4; j++) {
                const u64* gpj = &g_Gdup[chv[j] * GPITCH + h];
                float s = 0.f;
#pragma unroll
                for (int a = 0; a < 8; a++) {
                    float gv = __uint_as_float((unsigned)(gpj[a] & 0xFFFFFFFFull));
                    s = fmaf(gv, g_Wmid[kkv[j] * 8 + a], s);
                }
                acc[j] = s;
            }
            float4 o; o.x = acc[0]; o.y = acc[1]; o.z = acc[2]; o.w = acc[3];
            *(float4*)&out[(size_t)h * CTOT + c0] = o;
        }
    }
}

extern "C" void kernel_launch(void* const* d_in, const int* in_sizes, int n_in,
                              void* d_out, int out_size) {
    const float* x       = (const float*)d_in[0];
    const float* kernels = (const float*)d_in[1];
    if (n_in >= 2 && in_sizes[0] == NK * 24) {   // defensive: swapped order
        kernels = (const float*)d_in[0];
        x       = (const float*)d_in[1];
    }
    float* out = (float*)d_out;

    prep<<<(CIN * GPITCH + 255) / 256, 256>>>(x, kernels);

    dim3 grid(NQ / 256, (HP + HTILE - 1) / HTILE);  // (4, 769)
    conv_main<<<grid, 256>>>(out);
}

// round 7
// speedup vs baseline: 1.2105x; 1.2105x over previous
#include <cuda_runtime.h>

// Problem constants (from reference)
#define SEQ    4096
#define CIN    7
#define NK     586        // 585 regular kernels + 1 "last"
#define GLEN   12288      // SEQ * KW(3)
#define HP     12289      // output positions per channel-kernel row
#define GPITCH 12304      // GLEN + 16 (4 left pad + right slack), keeps 16B alignment
#define CTOT   4096       // 7*585 + 1
#define NQ     1024       // c-quads
#define HTILE  32

typedef unsigned long long u64;

// Scratch (allocation-free rule: __device__ globals)
__device__ u64   g_Gdup[CIN * GPITCH];     // duplicated signal: (g,g) as f32x2, g[i] = g_ch[i-4]
__device__ float g_Wmid[NK * 8];           // middle column of each 8x3 kernel (slow path)
__device__ ulonglong2 g_WqT[8 * NQ];       // TRANSPOSED packed weights: [tap][quad] -> {(w0,w1),(w2,w3)}

__device__ __forceinline__ u64 pk2(float lo, float hi) {
    u64 r; asm("mov.b64 %0, {%1,%2};" : "=l"(r) : "f"(lo), "f"(hi)); return r;
}
__device__ __forceinline__ u64 fma2(u64 a, u64 b, u64 c) {
    u64 d; asm("fma.rn.f32x2 %0, %1, %2, %3;" : "=l"(d) : "l"(a), "l"(b), "l"(c)); return d;
}

// ---- fused prep: mid-column weights, transposed packed weights, duplicated signal ----
__global__ void prep(const float* __restrict__ x, const float* __restrict__ kernels) {
    int idx = blockIdx.x * blockDim.x + threadIdx.x;
    if (idx < NK * 8) {
        int k = idx >> 3, a = idx & 7;
        g_Wmid[idx] = kernels[k * 24 + a * 3 + 1];
    }
    if (idx < NQ * 8) {
        int a = idx / NQ, q = idx - a * NQ;          // [tap][quad] layout
        float w[4];
#pragma unroll
        for (int j = 0; j < 4; j++) {
            int c = 4 * q + j;
            int k = (c == CTOT - 1) ? 585 : (c % 585);
            w[j] = kernels[k * 24 + a * 3 + 1];
        }
        ulonglong2 v; v.x = pk2(w[0], w[1]); v.y = pk2(w[2], w[3]);
        g_WqT[idx] = v;
    }
    if (idx < CIN * GPITCH) {
        int ch = idx / GPITCH;
        int i  = idx - ch * GPITCH;
        int t  = i - 4;
        float v = 0.f;
        if (t >= 0 && t < GLEN) {
            int s = t / 3;
            int j = t - s * 3;
            int src = s + j;
            if (src > SEQ - 1) src = SEQ - 1;
            v = x[src * CIN + ch];
        }
        g_Gdup[idx] = pk2(v, v);
    }
}

// ---- main kernel: one c-quad per thread, HTILE rows, one STG.128 per row,
//      SoA weight loads (warp-contiguous), pre-duplicated g window ----
__global__ void __launch_bounds__(256, 3) conv_main(float* __restrict__ out) {
    const int tid = threadIdx.x;
    const int q   = blockIdx.x * 256 + tid;     // [0, 1024), grid.x = 4
    const int c0  = q * 4;
    const int h0  = blockIdx.y * HTILE;

    const int ch0 = c0 / 585;
    const int c3  = c0 + 3;
    const int ch3 = (c3 == CTOT - 1) ? 0 : c3 / 585;

    const bool uniform  = (ch0 == ch3);
    const bool fulltile = (h0 + HTILE <= HP);

    if (uniform && fulltile) {
        // 8 taps x 2 packed weight pairs; warp-contiguous loads (4 wavefronts each)
        u64 W0[8], W1[8];
#pragma unroll
        for (int a = 0; a < 8; a++) {
            ulonglong2 t = g_WqT[a * NQ + q];
            W0[a] = t.x; W1[a] = t.y;
        }

        const u64* __restrict__ gp = &g_Gdup[ch0 * GPITCH + h0];   // 16B-aligned

        // Sliding window of 12 duplicated values, loaded as LDG.128 pairs (broadcast)
        u64 P[12];
        {
            ulonglong2 a0 = *(const ulonglong2*)(gp);
            ulonglong2 a1 = *(const ulonglong2*)(gp + 2);
            ulonglong2 a2 = *(const ulonglong2*)(gp + 4);
            ulonglong2 a3 = *(const ulonglong2*)(gp + 6);
            ulonglong2 a4 = *(const ulonglong2*)(gp + 8);
            ulonglong2 a5 = *(const ulonglong2*)(gp + 10);
            P[0] = a0.x; P[1] = a0.y; P[2]  = a1.x; P[3]  = a1.y;
            P[4] = a2.x; P[5] = a2.y; P[6]  = a3.x; P[7]  = a3.y;
            P[8] = a4.x; P[9] = a4.y; P[10] = a5.x; P[11] = a5.y;
        }

        char* op = (char*)(out + (size_t)h0 * CTOT + c0);
#pragma unroll
        for (int hb = 0; hb < HTILE; hb += 4) {
            ulonglong2 n0, n1;
            if (hb < HTILE - 4) {
                n0 = *(const ulonglong2*)(gp + hb + 12);
                n1 = *(const ulonglong2*)(gp + hb + 14);
            }
#pragma unroll
            for (int u = 0; u < 4; u++) {
                u64 a0 = 0ull, a1 = 0ull;
#pragma unroll
                for (int a = 0; a < 8; a++) {
                    u64 g2 = P[u + a];
                    a0 = fma2(g2, W0[a], a0);
                    a1 = fma2(g2, W1[a], a1);
                }
                ulonglong2 st; st.x = a0; st.y = a1;
                *(ulonglong2*)op = st;                  // STG.128: out[h][c0..c0+3]
                op += CTOT * sizeof(float);
            }
            if (hb < HTILE - 4) {
#pragma unroll
                for (int i = 0; i < 8; i++) P[i] = P[i + 4];
                P[8] = n0.x; P[9] = n0.y; P[10] = n1.x; P[11] = n1.y;
            }
        }
    } else {
        // Slow path: channel-crossing quads (7 of 1024) and the 1-row tail tile.
        int hEnd = min(h0 + HTILE, HP);
        int chv[4], kkv[4];
#pragma unroll
        for (int j = 0; j < 4; j++) {
            int c = c0 + j;
            if (c == CTOT - 1) { chv[j] = 0; kkv[j] = 585; }
            else               { chv[j] = c / 585; kkv[j] = c % 585; }
        }
        for (int h = h0; h < hEnd; h++) {
            float acc[4];
#pragma unroll
            for (int j = 0; j < 4; j++) {
                const u64* gpj = &g_Gdup[chv[j] * GPITCH + h];
                float s = 0.f;
#pragma unroll
                for (int a = 0; a < 8; a++) {
                    float gv = __uint_as_float((unsigned)(gpj[a] & 0xFFFFFFFFull));
                    s = fmaf(gv, g_Wmid[kkv[j] * 8 + a], s);
                }
                acc[j] = s;
            }
            float4 o; o.x = acc[0]; o.y = acc[1]; o.z = acc[2]; o.w = acc[3];
            *(float4*)&out[(size_t)h * CTOT + c0] = o;
        }
    }
}

extern "C" void kernel_launch(void* const* d_in, const int* in_sizes, int n_in,
                              void* d_out, int out_size) {
    const float* x       = (const float*)d_in[0];
    const float* kernels = (const float*)d_in[1];
    if (n_in >= 2 && in_sizes[0] == NK * 24) {   // defensive: swapped order
        kernels = (const float*)d_in[0];
        x       = (const float*)d_in[1];
    }
    float* out = (float*)d_out;

    prep<<<(CIN * GPITCH + 255) / 256, 256>>>(x, kernels);

    dim3 grid(NQ / 256, (HP + HTILE - 1) / HTILE);  // (4, 385)
    conv_main<<<grid, 256>>>(out);
}

// round 8
// speedup vs baseline: 1.6332x; 1.3492x over previous
#include <cuda_runtime.h>

// Problem constants (from reference)
#define SEQ    4096
#define CIN    7
#define NK     586        // 585 regular kernels + 1 "last"
#define GLEN   12288      // SEQ * KW(3)
#define HP     12289      // output positions per channel-kernel row
#define GPITCH 12304      // GLEN + 16 (4 left pad + right slack), keeps 16B alignment
#define CTOT   4096       // 7*585 + 1
#define NCP    2048       // c-pairs
#define HTILE  32

typedef unsigned long long u64;

// Scratch (allocation-free rule: __device__ globals)
__device__ u64   g_Gdup[CIN * GPITCH];   // duplicated signal: (g,g) as f32x2, g[i] = g_ch[i-4]
__device__ float g_Wmid[NK * 8];         // middle column of each 8x3 kernel (slow path)
__device__ u64   g_WpkT[8 * NCP];        // TRANSPOSED packed weights: [tap][cpair] -> (w_c0, w_c1)

__device__ __forceinline__ u64 pk2(float lo, float hi) {
    u64 r; asm("mov.b64 %0, {%1,%2};" : "=l"(r) : "f"(lo), "f"(hi)); return r;
}
__device__ __forceinline__ u64 fma2(u64 a, u64 b, u64 c) {
    u64 d; asm("fma.rn.f32x2 %0, %1, %2, %3;" : "=l"(d) : "l"(a), "l"(b), "l"(c)); return d;
}

// ---- fused prep: mid-column weights, transposed packed weight pairs, duplicated signal ----
__global__ void prep(const float* __restrict__ x, const float* __restrict__ kernels) {
    int idx = blockIdx.x * blockDim.x + threadIdx.x;
    if (idx < NK * 8) {
        int k = idx >> 3, a = idx & 7;
        g_Wmid[idx] = kernels[k * 24 + a * 3 + 1];
    }
    if (idx < 8 * NCP) {
        int a = idx / NCP, cp = idx - a * NCP;       // [tap][cpair] layout
        int c0 = 2 * cp, c1 = c0 + 1;
        int k0 = (c0 == CTOT - 1) ? 585 : (c0 % 585);
        int k1 = (c1 == CTOT - 1) ? 585 : (c1 % 585);
        g_WpkT[idx] = pk2(kernels[k0 * 24 + a * 3 + 1], kernels[k1 * 24 + a * 3 + 1]);
    }
    if (idx < CIN * GPITCH) {
        int ch = idx / GPITCH;
        int i  = idx - ch * GPITCH;
        int t  = i - 4;
        float v = 0.f;
        if (t >= 0 && t < GLEN) {
            int s = t / 3;
            int j = t - s * 3;
            int src = s + j;
            if (src > SEQ - 1) src = SEQ - 1;
            v = x[src * CIN + ch];
        }
        g_Gdup[idx] = pk2(v, v);
    }
}

// ---- main kernel: one c-pair per thread, HTILE rows, STG.64 per row,
//      SoA warp-contiguous weight loads, pre-duplicated g window ----
__global__ void __launch_bounds__(256, 4) conv_main(float* __restrict__ out) {
    const int tid = threadIdx.x;
    const int cp  = blockIdx.x * 256 + tid;     // [0, 2048), grid.x = 8
    const int c0  = cp * 2;
    const int h0  = blockIdx.y * HTILE;

    const int ch0 = c0 / 585;                   // c0 even -> never the special 4095
    const int c1  = c0 + 1;
    const int ch1 = (c1 == CTOT - 1) ? 0 : c1 / 585;

    const bool uniform  = (ch0 == ch1);
    const bool fulltile = (h0 + HTILE <= HP);

    if (uniform && fulltile) {
        // 8 packed weight pairs, warp-contiguous (8B/thread -> 2 wavefronts/load)
        u64 W[8];
#pragma unroll
        for (int a = 0; a < 8; a++) W[a] = g_WpkT[a * NCP + cp];

        const u64* __restrict__ gp = &g_Gdup[ch0 * GPITCH + h0];   // 16B-aligned

        // Sliding window of 12 duplicated values (24 regs), LDG.128 broadcast loads
        u64 P[12];
        {
            ulonglong2 a0 = *(const ulonglong2*)(gp);
            ulonglong2 a1 = *(const ulonglong2*)(gp + 2);
            ulonglong2 a2 = *(const ulonglong2*)(gp + 4);
            ulonglong2 a3 = *(const ulonglong2*)(gp + 6);
            ulonglong2 a4 = *(const ulonglong2*)(gp + 8);
            ulonglong2 a5 = *(const ulonglong2*)(gp + 10);
            P[0] = a0.x; P[1] = a0.y; P[2]  = a1.x; P[3]  = a1.y;
            P[4] = a2.x; P[5] = a2.y; P[6]  = a3.x; P[7]  = a3.y;
            P[8] = a4.x; P[9] = a4.y; P[10] = a5.x; P[11] = a5.y;
        }

        char* op = (char*)(out + (size_t)h0 * CTOT + c0);
#pragma unroll
        for (int hb = 0; hb < HTILE; hb += 4) {
            ulonglong2 n0, n1;
            if (hb < HTILE - 4) {
                n0 = *(const ulonglong2*)(gp + hb + 12);
                n1 = *(const ulonglong2*)(gp + hb + 14);
            }
#pragma unroll
            for (int u = 0; u < 4; u++) {
                u64 acc = 0ull;
#pragma unroll
                for (int a = 0; a < 8; a++) acc = fma2(P[u + a], W[a], acc);
                *(u64*)op = acc;                    // STG.64: out[h][c0..c0+1]
                op += CTOT * sizeof(float);
            }
            if (hb < HTILE - 4) {
#pragma unroll
                for (int i = 0; i < 8; i++) P[i] = P[i + 4];
                P[8] = n0.x; P[9] = n0.y; P[10] = n1.x; P[11] = n1.y;
            }
        }
    } else {
        // Slow path: channel-crossing pairs (4 of 2048) and the 1-row tail tile.
        int kk0 = (c0 == CTOT - 1) ? 585 : c0 % 585;
        int kk1 = (c1 == CTOT - 1) ? 585 : c1 % 585;
        int hEnd = min(h0 + HTILE, HP);
        for (int h = h0; h < hEnd; h++) {
            const u64* ga = &g_Gdup[ch0 * GPITCH + h];
            const u64* gb = &g_Gdup[ch1 * GPITCH + h];
            float s0 = 0.f, s1 = 0.f;
#pragma unroll
            for (int a = 0; a < 8; a++) {
                float va = __uint_as_float((unsigned)(ga[a] & 0xFFFFFFFFull));
                float vb = __uint_as_float((unsigned)(gb[a] & 0xFFFFFFFFull));
                s0 = fmaf(va, g_Wmid[kk0 * 8 + a], s0);
                s1 = fmaf(vb, g_Wmid[kk1 * 8 + a], s1);
            }
            float2 o; o.x = s0; o.y = s1;
            *(float2*)&out[(size_t)h * CTOT + c0] = o;
        }
    }
}

extern "C" void kernel_launch(void* const* d_in, const int* in_sizes, int n_in,
                              void* d_out, int out_size) {
    const float* x       = (const float*)d_in[0];
    const float* kernels = (const float*)d_in[1];
    if (n_in >= 2 && in_sizes[0] == NK * 24) {   // defensive: swapped order
        kernels = (const float*)d_in[0];
        x       = (const float*)d_in[1];
    }
    float* out = (float*)d_out;

    prep<<<(CIN * GPITCH + 255) / 256, 256>>>(x, kernels);

    dim3 grid(NCP / 256, (HP + HTILE - 1) / HTILE);  // (8, 385)
    conv_main<<<grid, 256>>>(out);
}